// round 4
// baseline (speedup 1.0000x reference)
#include <cuda_runtime.h>
#include <cstdint>

#define T_STEPS 4096
#define IN_SZ   1024
#define H       2048
#define MOD     256
#define NMOD    8
#define NCTA    128   // persistent CTAs for recurrence (< 148 SMs -> co-resident)

// Scratch (static device memory; no allocations allowed)
__device__ float g_U[(size_t)T_STEPS * H];                     // 32MB: U[t-1][r] = x·W_ih^T + b_ih + b_hh
__device__ __align__(16) unsigned long long g_hb[2 * H];       // packed (tag<<32 | f32 bits), double buffered

// ---------------------------------------------------------------------------
// relaxed 64-bit global load/store (single-word atomicity carries value+tag)
// ---------------------------------------------------------------------------
__device__ __forceinline__ unsigned long long ld_rlx(const unsigned long long* p) {
    unsigned long long v;
    asm volatile("ld.relaxed.gpu.global.b64 %0, [%1];" : "=l"(v) : "l"(p));
    return v;
}
__device__ __forceinline__ void st_rlx(unsigned long long* p, unsigned long long v) {
    asm volatile("st.relaxed.gpu.global.b64 [%0], %1;" :: "l"(p), "l"(v));
}

// ---------------------------------------------------------------------------
// Kernel 0: zero the h ring (tags must start at 0 on every launch)
// ---------------------------------------------------------------------------
__global__ void hb_init_kernel() {
    int i = blockIdx.x * blockDim.x + threadIdx.x;
    if (i < 2 * H) g_hb[i] = 0ull;
}

// ---------------------------------------------------------------------------
// Kernel 1: input projection, only for active (step, module) pairs.
// grid = (512, 8); CTA (bx, j) handles 8 consecutive active steps of module j:
//   t = 2^j * (8*bx + k + 1), k=0..7   (all per-module counts divisible by 8)
// 256 threads; thread tid computes row r = j*256 + tid for all 8 steps,
// streaming its W_ih row once (float4, L2-resident) against 8 x-vectors in smem.
// ---------------------------------------------------------------------------
__global__ __launch_bounds__(256) void input_gemm_kernel(
    const float* __restrict__ x, const float* __restrict__ W_ih,
    const float* __restrict__ b_ih, const float* __restrict__ b_hh)
{
    const int j  = blockIdx.y;
    const int nb = (T_STEPS >> j) >> 3;
    const int bx = blockIdx.x;
    if (bx >= nb) return;
    const int p   = 1 << j;
    const int tid = threadIdx.x;

    __shared__ float4 xs[8][IN_SZ / 4];            // 32 KB
    #pragma unroll
    for (int k = 0; k < 8; k++) {
        int t = p * (bx * 8 + k + 1);              // 1-indexed active step
        const float4* xr = (const float4*)(x + (size_t)(t - 1) * IN_SZ);
        xs[k][tid] = xr[tid];
    }
    __syncthreads();

    const int r = j * MOD + tid;
    const float4* wr = (const float4*)(W_ih + (size_t)r * IN_SZ);
    float acc[8] = {0.f, 0.f, 0.f, 0.f, 0.f, 0.f, 0.f, 0.f};
    #pragma unroll 2
    for (int q = 0; q < IN_SZ / 4; q++) {
        const float4 w = wr[q];
        #pragma unroll
        for (int k = 0; k < 8; k++) {
            const float4 xv = xs[k][q];            // warp-broadcast LDS
            acc[k] = fmaf(w.x, xv.x, fmaf(w.y, xv.y, fmaf(w.z, xv.z, fmaf(w.w, xv.w, acc[k]))));
        }
    }
    const float b = b_ih[r] + b_hh[r];
    #pragma unroll
    for (int k = 0; k < 8; k++) {
        int t = p * (bx * 8 + k + 1);
        g_U[(size_t)(t - 1) * H + r] = acc[k] + b;
    }
}

// ---------------------------------------------------------------------------
// Kernel 2: persistent recurrence. 128 CTAs x 256 threads, 1 CTA/SM.
// Warp w of CTA c owns rows r0 = w*256 + 2c, r1 = r0+1 (2 rows of module w).
// W_hh rows live in registers: lane l holds columns {128q + 4l .. +3}, q<16.
// Per step t:
//   - every thread stages 8 tagged h-columns (one per module) from the global
//     slot ring into smem (double buffered by t&1) with exact-tag spins,
//   - one __syncthreads,
//   - active warps (t % 2^w == 0) do the 2x2048 dot with 8 independent FMA
//     chains, 32-lane butterfly reduce, tanh, publish packed (val, tag=t) to
//     slot (t>>w)&1, and every warp writes its two output floats.
// Spin budget converts any unforeseen protocol bug into a finite wrong run
// instead of a container-killing hang.
// ---------------------------------------------------------------------------
__global__ __launch_bounds__(256, 1) void recurrence_kernel(
    const float* __restrict__ W_hh, float* __restrict__ out)
{
    __shared__ float hsm[2][H];                   // 16 KB double-buffered h stage

    const int tid = threadIdx.x;
    const int w   = tid >> 5;
    const int l   = tid & 31;
    const int c   = blockIdx.x;                   // 0..127
    const int r0  = w * MOD + 2 * c;
    const int r1  = r0 + 1;

    // This warp's two W_hh rows -> registers (128 f32 regs/lane).
    float4 w0[16], w1[16];
    #pragma unroll
    for (int q = 0; q < 16; q++) {
        w0[q] = *(const float4*)(W_hh + (size_t)r0 * H + q * 128 + l * 4);
        w1[q] = *(const float4*)(W_hh + (size_t)r1 * H + q * 128 + l * 4);
    }

    float hc0 = 0.f, hc1 = 0.f;                   // current h of owned rows (lane 0 authoritative)
    const unsigned pmask = (1u << w) - 1u;        // warp active iff (t & pmask)==0
    int budget = 1 << 24;                         // hang guard (never hit in correct runs)

    for (int t = 1; t <= T_STEPS; t++) {
        const bool act = ((unsigned)t & pmask) == 0u;

        // Prefetch U for this step early (overlaps the poll below).
        float2 uu = make_float2(0.f, 0.f);
        if (act) uu = *(const float2*)(g_U + (size_t)(t - 1) * H + r0);

        // ---- stage h_{t-1} into hsm[t&1]; thread covers col = tid + 256*i ----
        float* hs = hsm[t & 1];
        unsigned long long v[8];
        const unsigned long long* ap[8];
        unsigned s0[8];
        #pragma unroll
        for (int i = 0; i < 8; i++) {
            const int col = tid + 256 * i;                        // a column of module i
            s0[i] = (unsigned)(t - 1) & ~((1u << i) - 1u);        // exact expected tag
            const int slot = (int)((s0[i] >> i) & 1u);
            ap[i] = &g_hb[slot * H + col];
            v[i]  = ld_rlx(ap[i]);                                // 8 polls in flight (MLP=8)
        }
        #pragma unroll
        for (int i = 7; i >= 0; i--) {                            // slowest (small-period) cols last
            while ((unsigned)(v[i] >> 32) != s0[i]) {
                if (--budget < 0) break;                          // hang guard
                v[i] = ld_rlx(ap[i]);
            }
            hs[tid + 256 * i] = __uint_as_float((unsigned)v[i]);
        }
        __syncthreads();

        // ---- recurrent dot for active warps: 8 independent FMA chains ----
        if (act) {
            float a0x = 0.f, a0y = 0.f, a0z = 0.f, a0w = 0.f;
            float a1x = 0.f, a1y = 0.f, a1z = 0.f, a1w = 0.f;
            #pragma unroll
            for (int q = 0; q < 16; q++) {
                const float4 hv = *(const float4*)(hs + q * 128 + l * 4);
                a0x = fmaf(hv.x, w0[q].x, a0x);
                a0y = fmaf(hv.y, w0[q].y, a0y);
                a0z = fmaf(hv.z, w0[q].z, a0z);
                a0w = fmaf(hv.w, w0[q].w, a0w);
                a1x = fmaf(hv.x, w1[q].x, a1x);
                a1y = fmaf(hv.y, w1[q].y, a1y);
                a1z = fmaf(hv.z, w1[q].z, a1z);
                a1w = fmaf(hv.w, w1[q].w, a1w);
            }
            float a0 = (a0x + a0y) + (a0z + a0w);
            float a1 = (a1x + a1y) + (a1z + a1w);
            #pragma unroll
            for (int off = 16; off >= 1; off >>= 1) {
                a0 += __shfl_xor_sync(0xffffffffu, a0, off);
                a1 += __shfl_xor_sync(0xffffffffu, a1, off);
            }
            if (l == 0) {
                hc0 = tanhf(uu.x + a0);
                hc1 = tanhf(uu.y + a1);
                const int slot = (t >> w) & 1;
                const unsigned long long tag = ((unsigned long long)(unsigned)t) << 32;
                st_rlx(&g_hb[slot * H + r0], tag | (unsigned long long)__float_as_uint(hc0));
                st_rlx(&g_hb[slot * H + r1], tag | (unsigned long long)__float_as_uint(hc1));
            }
        }
        // ---- output (every warp, every step: fresh or carried value) ----
        if (l == 0) {
            *(float2*)(out + (size_t)(t - 1) * H + r0) = make_float2(hc0, hc1);
        }
    }
}

// ---------------------------------------------------------------------------
extern "C" void kernel_launch(void* const* d_in, const int* in_sizes, int n_in,
                              void* d_out, int out_size)
{
    const float* x    = (const float*)d_in[0];
    const float* W_ih = (const float*)d_in[1];
    const float* W_hh = (const float*)d_in[2];
    const float* b_ih = (const float*)d_in[3];
    const float* b_hh = (const float*)d_in[4];
    float* out = (float*)d_out;

    hb_init_kernel<<<16, 256>>>();
    input_gemm_kernel<<<dim3(512, NMOD), 256>>>(x, W_ih, b_ih, b_hh);
    recurrence_kernel<<<NCTA, 256>>>(W_hh, out);
}

// round 5
// speedup vs baseline: 1.0299x; 1.0299x over previous
#include <cuda_runtime.h>
#include <cstdint>

#define T_STEPS 4096
#define IN_SZ   1024
#define H       2048
#define MOD     256
#define NMOD    8
#define NCTA    128   // persistent CTAs for recurrence (< 148 SMs -> co-resident)

// Scratch (static device memory; no allocations allowed)
__device__ float g_U[(size_t)T_STEPS * H];        // 32MB: U[t-1][r] = x·W_ih^T + b_ih + b_hh
__device__ float g_hv[2][H];                      // published h, double-buffered by module-epoch parity
__device__ __align__(32) unsigned g_cnt[NMOD];    // monotonic readiness counters, ONE 32B sector

// ---------------------------------------------------------------------------
// memory-model primitives
// ---------------------------------------------------------------------------
__device__ __forceinline__ unsigned ld_acq_u32(const unsigned* p) {
    unsigned v;
    asm volatile("ld.acquire.gpu.global.u32 %0, [%1];" : "=r"(v) : "l"(p));
    return v;
}
__device__ __forceinline__ void st_rlx_f32(float* p, float v) {
    asm volatile("st.relaxed.gpu.global.f32 [%0], %1;" :: "l"(p), "f"(v));
}
__device__ __forceinline__ void red_rel_add(unsigned* p, unsigned v) {
    asm volatile("red.release.gpu.global.add.u32 [%0], %1;" :: "l"(p), "r"(v));
}

// ---------------------------------------------------------------------------
// Kernel 0: zero the publish buffers + counters (fresh state every launch)
// ---------------------------------------------------------------------------
__global__ void init_kernel() {
    int i = blockIdx.x * blockDim.x + threadIdx.x;
    if (i < 2 * H) ((float*)g_hv)[i] = 0.f;
    if (i < NMOD)  g_cnt[i] = 0u;
}

// ---------------------------------------------------------------------------
// Kernel 1: input projection, only for active (step, module) pairs.
// grid = (512, 8); CTA (bx, j) handles 8 consecutive active steps of module j:
//   t = 2^j * (8*bx + k + 1), k=0..7
// 256 threads; thread tid computes row r = j*256 + tid for all 8 steps,
// streaming its W_ih row once (float4, L2-resident) against 8 x-vectors in smem.
// ---------------------------------------------------------------------------
__global__ __launch_bounds__(256) void input_gemm_kernel(
    const float* __restrict__ x, const float* __restrict__ W_ih,
    const float* __restrict__ b_ih, const float* __restrict__ b_hh)
{
    const int j  = blockIdx.y;
    const int nb = (T_STEPS >> j) >> 3;
    const int bx = blockIdx.x;
    if (bx >= nb) return;
    const int p   = 1 << j;
    const int tid = threadIdx.x;

    __shared__ float4 xs[8][IN_SZ / 4];            // 32 KB
    #pragma unroll
    for (int k = 0; k < 8; k++) {
        int t = p * (bx * 8 + k + 1);              // 1-indexed active step
        const float4* xr = (const float4*)(x + (size_t)(t - 1) * IN_SZ);
        xs[k][tid] = xr[tid];
    }
    __syncthreads();

    const int r = j * MOD + tid;
    const float4* wr = (const float4*)(W_ih + (size_t)r * IN_SZ);
    float acc[8] = {0.f, 0.f, 0.f, 0.f, 0.f, 0.f, 0.f, 0.f};
    #pragma unroll 2
    for (int q = 0; q < IN_SZ / 4; q++) {
        const float4 w = wr[q];
        #pragma unroll
        for (int k = 0; k < 8; k++) {
            const float4 xv = xs[k][q];
            acc[k] = fmaf(w.x, xv.x, fmaf(w.y, xv.y, fmaf(w.z, xv.z, fmaf(w.w, xv.w, acc[k]))));
        }
    }
    const float b = b_ih[r] + b_hh[r];
    #pragma unroll
    for (int k = 0; k < 8; k++) {
        int t = p * (bx * 8 + k + 1);
        g_U[(size_t)(t - 1) * H + r] = acc[k] + b;
    }
}

// ---------------------------------------------------------------------------
// Kernel 2: persistent recurrence. 128 CTAs x 256 threads, 1 CTA/SM.
// Warp w of CTA c owns rows r0 = w*256 + 2c, r1 = r0+1 (2 rows of module w).
// W_hh rows live in registers (128 f32/lane).
// Per step t (1-indexed):
//   - modules needing refresh: j < nref = tz(t-1)+1 (all 8 at t=1). For each,
//     all threads spin warp-converged on g_cnt[j] (ld.acquire, 32B sector),
//     then re-read that module's 256 columns into the PERSISTENT smem h copy.
//   - __syncthreads; active warps (t % 2^w == 0) do the 2x2048 dot with 8
//     independent FMA chains, butterfly-reduce, tanh, publish to slot
//     (t>>w)&1 via st.relaxed and red.release the module counter.
//   - every warp writes its 2 output floats; second __syncthreads protects
//     the smem h copy from the next step's refresh.
// ---------------------------------------------------------------------------
__global__ __launch_bounds__(256, 1) void recurrence_kernel(
    const float* __restrict__ W_hh, float* __restrict__ out)
{
    __shared__ __align__(16) float hsm[H];        // persistent staged h (8 KB)

    const int tid = threadIdx.x;
    const int w   = tid >> 5;
    const int l   = tid & 31;
    const int c   = blockIdx.x;                   // 0..127
    const int r0  = w * MOD + 2 * c;
    const int r1  = r0 + 1;

    // This warp's two W_hh rows -> registers.
    float4 w0[16], w1[16];
    #pragma unroll
    for (int q = 0; q < 16; q++) {
        w0[q] = *(const float4*)(W_hh + (size_t)r0 * H + q * 128 + l * 4);
        w1[q] = *(const float4*)(W_hh + (size_t)r1 * H + q * 128 + l * 4);
    }

    float hc0 = 0.f, hc1 = 0.f;                   // current h of owned rows (lane 0 authoritative)
    const unsigned pmask = (1u << w) - 1u;        // warp active iff (t & pmask)==0
    int budget = 1 << 24;                         // hang guard

    for (int t = 1; t <= T_STEPS; t++) {
        const unsigned tm = (unsigned)(t - 1);
        int nref = tm ? __ffs((int)tm) : NMOD;    // tz(tm)+1, or all at t=1
        if (nref > NMOD) nref = NMOD;
        const bool act = ((unsigned)t & pmask) == 0u;

        // Prefetch U for this step (overlaps the counter polls below).
        float2 uu = make_float2(0.f, 0.f);
        if (act) uu = *(const float2*)(g_U + (size_t)tm * H + r0);

        // ---- poll counters + refresh changed modules (high j first: those
        //      counters were satisfied long ago; module 0 — freshest — last) ----
        #pragma unroll
        for (int j = NMOD - 1; j >= 0; j--) {
            if (j < nref) {
                const unsigned expect = 128u * (tm >> j);
                unsigned cv = ld_acq_u32(&g_cnt[j]);
                while (cv < expect) {
                    if (--budget < 0) break;      // hang guard
                    cv = ld_acq_u32(&g_cnt[j]);
                }
                const int slot = (int)((tm >> j) & 1u);
                hsm[j * MOD + tid] = g_hv[slot][j * MOD + tid];
            }
        }
        __syncthreads();

        // ---- recurrent dot for active warps: 8 independent FMA chains ----
        if (act) {
            float a0x = 0.f, a0y = 0.f, a0z = 0.f, a0w = 0.f;
            float a1x = 0.f, a1y = 0.f, a1z = 0.f, a1w = 0.f;
            #pragma unroll
            for (int q = 0; q < 16; q++) {
                const float4 hv = *(const float4*)(hsm + q * 128 + l * 4);
                a0x = fmaf(hv.x, w0[q].x, a0x);
                a0y = fmaf(hv.y, w0[q].y, a0y);
                a0z = fmaf(hv.z, w0[q].z, a0z);
                a0w = fmaf(hv.w, w0[q].w, a0w);
                a1x = fmaf(hv.x, w1[q].x, a1x);
                a1y = fmaf(hv.y, w1[q].y, a1y);
                a1z = fmaf(hv.z, w1[q].z, a1z);
                a1w = fmaf(hv.w, w1[q].w, a1w);
            }
            float a0 = (a0x + a0y) + (a0z + a0w);
            float a1 = (a1x + a1y) + (a1z + a1w);
            #pragma unroll
            for (int off = 16; off >= 1; off >>= 1) {
                a0 += __shfl_xor_sync(0xffffffffu, a0, off);
                a1 += __shfl_xor_sync(0xffffffffu, a1, off);
            }
            if (l == 0) {
                hc0 = tanhf(uu.x + a0);
                hc1 = tanhf(uu.y + a1);
                const int slot = (t >> w) & 1;
                st_rlx_f32(&g_hv[slot][r0], hc0);
                st_rlx_f32(&g_hv[slot][r1], hc1);
                red_rel_add(&g_cnt[w], 1u);       // release: orders the 2 stores above
            }
        }
        // ---- output (every warp, every step: fresh or carried value) ----
        if (l == 0) {
            *(float2*)(out + (size_t)tm * H + r0) = make_float2(hc0, hc1);
        }
        __syncthreads();                          // dot done before next refresh touches hsm
    }
}

// ---------------------------------------------------------------------------
extern "C" void kernel_launch(void* const* d_in, const int* in_sizes, int n_in,
                              void* d_out, int out_size)
{
    const float* x    = (const float*)d_in[0];
    const float* W_ih = (const float*)d_in[1];
    const float* W_hh = (const float*)d_in[2];
    const float* b_ih = (const float*)d_in[3];
    const float* b_hh = (const float*)d_in[4];
    float* out = (float*)d_out;

    init_kernel<<<16, 256>>>();
    input_gemm_kernel<<<dim3(512, NMOD), 256>>>(x, W_ih, b_ih, b_hh);
    recurrence_kernel<<<NCTA, 256>>>(W_hh, out);
}